// round 7
// baseline (speedup 1.0000x reference)
#include <cuda_runtime.h>
#include <cuda_bf16.h>
#include <cstdint>
#include <cstddef>
#include <math.h>

#define NN 1024
#define LL 2048
#define HH 128

// ---------------- scratch (device globals; no allocation) ----------------
static __device__ float g_k[(size_t)NN * LL * HH];   // 1 GiB
static __device__ float g_logits[(size_t)NN * LL];
static __device__ float g_x[NN * HH];
static __device__ float g_state[NN * HH];
static __device__ float g_q[NN * HH];

// ---------------- math helpers ----------------
__device__ __forceinline__ float ex2f(float x){ float r; asm("ex2.approx.f32 %0, %1;" : "=f"(r) : "f"(x)); return r; }
__device__ __forceinline__ float rcpaf(float x){ float r; asm("rcp.approx.f32 %0, %1;" : "=f"(r) : "f"(x)); return r; }

// tanh(x) = 1 - 2/(1+e^{2x}); ex2 + rcp + one Newton step  (~1e-7 abs err)
__device__ __forceinline__ float acc_tanh(float x){
    float y = fminf(x * 2.8853900817779268f, 80.0f);   // 2/ln(2)
    float e = ex2f(y);
    float d = e + 1.0f;
    float r = rcpaf(d);
    r = r * fmaf(-d, r, 2.0f);                         // Newton
    return fmaf(-2.0f, r, 1.0f);
}

#define FMA2(d, a, b) asm("fma.rn.f32x2 %0, %1, %2, %0;" : "+l"(d) : "l"(a), "l"(b))

// ---------------- init decoder input to ones ----------------
__global__ void init_x_kernel(){
    int i = blockIdx.x * blockDim.x + threadIdx.x;
    if (i < NN * HH) g_x[i] = 1.0f;
}

// ---------------- GRU cell + q projection ----------------
// 8 batch rows per block, 128 threads (thread = output channel j).
#define GR 8
__global__ void __launch_bounds__(HH) gru_kernel(
    const float* __restrict__ x_in, const float* __restrict__ h_in,
    const float* __restrict__ W_ih, const float* __restrict__ W_hh,
    const float* __restrict__ b_ih, const float* __restrict__ b_hh,
    const float* __restrict__ Wq)
{
    __shared__ float x_s[GR][HH];
    __shared__ float h_s[GR][HH];
    __shared__ float hn_s[GR][HH];
    const int n0 = blockIdx.x * GR;
    const int j  = threadIdx.x;
    for (int r = 0; r < GR; r++){
        x_s[r][j] = x_in[(n0 + r) * HH + j];
        h_s[r][j] = h_in[(n0 + r) * HH + j];
    }
    __syncthreads();

    float ar[GR], az[GR], anx[GR], anh[GR];
    #pragma unroll
    for (int r = 0; r < GR; r++){ ar[r] = az[r] = anx[r] = anh[r] = 0.0f; }

    const float4* Wr = (const float4*)(W_ih + (size_t)j * HH);
    const float4* Wz = (const float4*)(W_ih + (size_t)(HH + j) * HH);
    const float4* Wn = (const float4*)(W_ih + (size_t)(2 * HH + j) * HH);
    const float4* Vr = (const float4*)(W_hh + (size_t)j * HH);
    const float4* Vz = (const float4*)(W_hh + (size_t)(HH + j) * HH);
    const float4* Vn = (const float4*)(W_hh + (size_t)(2 * HH + j) * HH);

    for (int h4 = 0; h4 < HH / 4; h4++){
        float4 wr = Wr[h4], wz = Wz[h4], wn = Wn[h4];
        float4 vr = Vr[h4], vz = Vz[h4], vn = Vn[h4];
        #pragma unroll
        for (int r = 0; r < GR; r++){
            float4 xx = *(const float4*)&x_s[r][h4 * 4];
            float4 hh = *(const float4*)&h_s[r][h4 * 4];
            ar[r]  += wr.x*xx.x + wr.y*xx.y + wr.z*xx.z + wr.w*xx.w
                    + vr.x*hh.x + vr.y*hh.y + vr.z*hh.z + vr.w*hh.w;
            az[r]  += wz.x*xx.x + wz.y*xx.y + wz.z*xx.z + wz.w*xx.w
                    + vz.x*hh.x + vz.y*hh.y + vz.z*hh.z + vz.w*hh.w;
            anx[r] += wn.x*xx.x + wn.y*xx.y + wn.z*xx.z + wn.w*xx.w;
            anh[r] += vn.x*hh.x + vn.y*hh.y + vn.z*hh.z + vn.w*hh.w;
        }
    }
    const float br  = b_ih[j] + b_hh[j];
    const float bz  = b_ih[HH + j] + b_hh[HH + j];
    const float bnx = b_ih[2 * HH + j];
    const float bnh = b_hh[2 * HH + j];
    #pragma unroll
    for (int r = 0; r < GR; r++){
        float rr = 1.0f / (1.0f + expf(-(ar[r] + br)));
        float zz = 1.0f / (1.0f + expf(-(az[r] + bz)));
        float nn = tanhf(anx[r] + bnx + rr * (anh[r] + bnh));
        float hp = (1.0f - zz) * nn + zz * h_s[r][j];
        hn_s[r][j] = hp;
        g_state[(n0 + r) * HH + j] = hp;
    }
    __syncthreads();
    float aq[GR];
    #pragma unroll
    for (int r = 0; r < GR; r++) aq[r] = 0.0f;
    const float4* Q = (const float4*)(Wq + (size_t)j * HH);
    for (int h4 = 0; h4 < HH / 4; h4++){
        float4 wq = Q[h4];
        #pragma unroll
        for (int r = 0; r < GR; r++){
            float4 hh = *(const float4*)&hn_s[r][h4 * 4];
            aq[r] += wq.x*hh.x + wq.y*hh.y + wq.z*hh.z + wq.w*hh.w;
        }
    }
    #pragma unroll
    for (int r = 0; r < GR; r++) g_q[(n0 + r) * HH + j] = aq[r];
}

// ---------------- fused k-GEMM + step-1 score ----------------
// grid (32, 1024): blockIdx.y = n, blockIdx.x = 64-row L-tile.
// 256 threads: lane to = tid&31 owns outputs o = 4*to+oi; warp tr = tid>>5
// owns rows l = l0 + tr + 8*rr (rr 0..7).
// k accumulated as packed f32x2 (FFMA2); epilogue writes k + fused
// logits1[n,l] = sum_o w[o]*tanh(q1[n,o] + k[n,l,o]) via warp shfl reduce.
__global__ void __launch_bounds__(256) kq_kernel(
    const float* __restrict__ eo, const float* __restrict__ Wk,
    const float* __restrict__ w_score, const float* __restrict__ q)
{
    const int n  = blockIdx.y;
    const int l0 = blockIdx.x * 64;
    const int to = threadIdx.x & 31;
    const int tr = threadIdx.x >> 5;

    unsigned long long acc[4][8];
    #pragma unroll
    for (int oi = 0; oi < 4; oi++)
        #pragma unroll
        for (int rr = 0; rr < 8; rr++) acc[oi][rr] = 0ULL;

    const float* wk_b = Wk + (size_t)(4 * to) * HH;
    const float* eo_b = eo + ((size_t)n * LL + l0 + tr) * HH;

    #pragma unroll 8
    for (int h4 = 0; h4 < HH / 4; h4++){
        ulonglong2 w[4];
        #pragma unroll
        for (int oi = 0; oi < 4; oi++)
            w[oi] = *(const ulonglong2*)(wk_b + oi * HH + h4 * 4);
        #pragma unroll
        for (int rr = 0; rr < 8; rr++){
            ulonglong2 e = *(const ulonglong2*)(eo_b + rr * 8 * HH + h4 * 4);
            #pragma unroll
            for (int oi = 0; oi < 4; oi++){
                FMA2(acc[oi][rr], w[oi].x, e.x);
                FMA2(acc[oi][rr], w[oi].y, e.y);
            }
        }
    }

    const float4 qv = *(const float4*)(q + (size_t)n * HH + 4 * to);
    const float4 wv = *(const float4*)(w_score + 4 * to);

    #pragma unroll
    for (int rr = 0; rr < 8; rr++){
        const int l = l0 + tr + 8 * rr;
        float kv[4];
        #pragma unroll
        for (int oi = 0; oi < 4; oi++){
            unsigned long long a = acc[oi][rr];
            float lo = __uint_as_float((unsigned)(a & 0xffffffffULL));
            float hi = __uint_as_float((unsigned)(a >> 32));
            kv[oi] = lo + hi;
        }
        *(float4*)(g_k + ((size_t)n * LL + l) * HH + 4 * to) =
            make_float4(kv[0], kv[1], kv[2], kv[3]);

        float s = wv.x * acc_tanh(qv.x + kv[0])
                + wv.y * acc_tanh(qv.y + kv[1])
                + wv.z * acc_tanh(qv.z + kv[2])
                + wv.w * acc_tanh(qv.w + kv[3]);
        #pragma unroll
        for (int off = 16; off > 0; off >>= 1)
            s += __shfl_xor_sync(0xffffffffu, s, off);
        if (to == 0) g_logits[(size_t)n * LL + l] = s;
    }
}

// ---------------- step-2 score: read k scratch ----------------
// 8 warps/block, warp = one (n,l) row; memory bound.
__global__ void __launch_bounds__(256) score2_kernel(
    const float* __restrict__ w_score, const float* __restrict__ q)
{
    const size_t row  = (size_t)blockIdx.x * 8 + (threadIdx.x >> 5);
    const int    lane = threadIdx.x & 31;
    const int    n    = (int)(row >> 11);           // row / LL

    const float4 kv = *(const float4*)(g_k + row * HH + 4 * lane);
    const float4 qv = *(const float4*)(q + (size_t)n * HH + 4 * lane);
    const float4 wv = *(const float4*)(w_score + 4 * lane);

    float s = wv.x * acc_tanh(qv.x + kv.x)
            + wv.y * acc_tanh(qv.y + kv.y)
            + wv.z * acc_tanh(qv.z + kv.z)
            + wv.w * acc_tanh(qv.w + kv.w);
    #pragma unroll
    for (int off = 16; off > 0; off >>= 1)
        s += __shfl_xor_sync(0xffffffffu, s, off);
    if (lane == 0) g_logits[row] = s;
}

// ---------------- softmax + argmax (+ gather next input) ----------------
// block per n, 256 threads, 8 logits/thread.
__global__ void __launch_bounds__(256) softmax_kernel(
    const float* __restrict__ enc_in, float* __restrict__ out,
    int step, int do_gather)
{
    __shared__ float smax[256];
    __shared__ int   sidx[256];
    __shared__ float ssum[256];
    const int n   = blockIdx.x;
    const int tid = threadIdx.x;
    const float* lg = g_logits + (size_t)n * LL;

    float v[8];
    float vmax = -1e30f; int vidx = 0;
    #pragma unroll
    for (int i = 0; i < 8; i++){
        int l = tid + i * 256;
        v[i] = lg[l];
        if (v[i] > vmax){ vmax = v[i]; vidx = l; }
    }
    smax[tid] = vmax; sidx[tid] = vidx;
    __syncthreads();
    for (int s = 128; s > 0; s >>= 1){
        if (tid < s){
            float ov = smax[tid + s]; int oi = sidx[tid + s];
            if (ov > smax[tid] || (ov == smax[tid] && oi < sidx[tid])){
                smax[tid] = ov; sidx[tid] = oi;
            }
        }
        __syncthreads();
    }
    const float m   = smax[0];
    const int   idx = sidx[0];
    __syncthreads();

    float e[8];
    float loc = 0.0f;
    #pragma unroll
    for (int i = 0; i < 8; i++){ e[i] = expf(v[i] - m); loc += e[i]; }
    ssum[tid] = loc;
    __syncthreads();
    for (int s = 128; s > 0; s >>= 1){
        if (tid < s) ssum[tid] += ssum[tid + s];
        __syncthreads();
    }
    const float inv = 1.0f / ssum[0];

    float* orow = out + ((size_t)n * 2 + step) * LL;
    #pragma unroll
    for (int i = 0; i < 8; i++) orow[tid + i * 256] = e[i] * inv;

    if (do_gather && tid < HH)
        g_x[n * HH + tid] = enc_in[((size_t)n * LL + idx) * HH + tid];
}

// ---------------- launch ----------------
extern "C" void kernel_launch(void* const* d_in, const int* in_sizes, int n_in,
                              void* d_out, int out_size)
{
    const float* enc_in  = (const float*)d_in[0];
    const float* enc_out = (const float*)d_in[1];
    const float* state0  = (const float*)d_in[2];
    const float* W_ih    = (const float*)d_in[3];
    const float* W_hh    = (const float*)d_in[4];
    const float* b_ih    = (const float*)d_in[5];
    const float* b_hh    = (const float*)d_in[6];
    const float* Wq      = (const float*)d_in[7];
    const float* Wk      = (const float*)d_in[8];
    const float* w_score = (const float*)d_in[9];
    float* out = (float*)d_out;

    float *p_x, *p_state, *p_q;
    cudaGetSymbolAddress((void**)&p_x, g_x);
    cudaGetSymbolAddress((void**)&p_state, g_state);
    cudaGetSymbolAddress((void**)&p_q, g_q);

    // step 1
    init_x_kernel<<<(NN * HH + 255) / 256, 256>>>();
    gru_kernel<<<NN / GR, HH>>>(p_x, state0, W_ih, W_hh, b_ih, b_hh, Wq);
    kq_kernel<<<dim3(LL / 64, NN), 256>>>(enc_out, Wk, w_score, p_q);
    softmax_kernel<<<NN, 256>>>(enc_in, out, 0, 1);
    // step 2
    gru_kernel<<<NN / GR, HH>>>(p_x, p_state, W_ih, W_hh, b_ih, b_hh, Wq);
    score2_kernel<<<(int)(((size_t)NN * LL) / 8), 256>>>(w_score, p_q);
    softmax_kernel<<<NN, 256>>>(enc_in, out, 1, 0);
}

// round 8
// speedup vs baseline: 1.3430x; 1.3430x over previous
#include <cuda_runtime.h>
#include <cuda_bf16.h>
#include <cstdint>
#include <cstddef>
#include <math.h>

#define NN 1024
#define LL 2048
#define HH 128

// ---------------- scratch (device globals; no allocation) ----------------
static __device__ float g_k[(size_t)NN * LL * HH];   // 1 GiB
static __device__ float g_logits[(size_t)NN * LL];
static __device__ float g_x[NN * HH];
static __device__ float g_state[NN * HH];
static __device__ float g_q[NN * HH];
static __device__ float g_WkT[HH * HH];              // Wk transposed: [h][o]

// ---------------- math helpers ----------------
__device__ __forceinline__ float ex2f(float x){ float r; asm("ex2.approx.f32 %0, %1;" : "=f"(r) : "f"(x)); return r; }
__device__ __forceinline__ float rcpaf(float x){ float r; asm("rcp.approx.f32 %0, %1;" : "=f"(r) : "f"(x)); return r; }

// tanh(x) = 1 - 2/(1+e^{2x}); ex2 + rcp + one Newton step  (~1e-7 abs err)
__device__ __forceinline__ float acc_tanh(float x){
    float y = fminf(x * 2.8853900817779268f, 80.0f);   // 2/ln(2)
    float e = ex2f(y);
    float d = e + 1.0f;
    float r = rcpaf(d);
    r = r * fmaf(-d, r, 2.0f);                         // Newton
    return fmaf(-2.0f, r, 1.0f);
}

#define FMA2(d, a, b) asm("fma.rn.f32x2 %0, %1, %2, %0;" : "+l"(d) : "l"(a), "l"(b))

__device__ __forceinline__ unsigned long long pack2(float lo, float hi){
    return (unsigned long long)__float_as_uint(lo)
         | ((unsigned long long)__float_as_uint(hi) << 32);
}

// ---------------- init decoder input to ones ----------------
__global__ void init_x_kernel(){
    int i = blockIdx.x * blockDim.x + threadIdx.x;
    if (i < NN * HH) g_x[i] = 1.0f;
}

// ---------------- transpose Wk (64 KB, once per replay) ----------------
__global__ void __launch_bounds__(HH) transpose_wk_kernel(const float* __restrict__ Wk){
    const int h = blockIdx.x;       // 128 blocks
    const int o = threadIdx.x;      // 128 threads
    g_WkT[h * HH + o] = Wk[o * HH + h];
}

// ---------------- GRU cell + q projection ----------------
// 8 batch rows per block, 128 threads (thread = output channel j).
#define GR 8
__global__ void __launch_bounds__(HH) gru_kernel(
    const float* __restrict__ x_in, const float* __restrict__ h_in,
    const float* __restrict__ W_ih, const float* __restrict__ W_hh,
    const float* __restrict__ b_ih, const float* __restrict__ b_hh,
    const float* __restrict__ Wq)
{
    __shared__ float x_s[GR][HH];
    __shared__ float h_s[GR][HH];
    __shared__ float hn_s[GR][HH];
    const int n0 = blockIdx.x * GR;
    const int j  = threadIdx.x;
    for (int r = 0; r < GR; r++){
        x_s[r][j] = x_in[(n0 + r) * HH + j];
        h_s[r][j] = h_in[(n0 + r) * HH + j];
    }
    __syncthreads();

    float ar[GR], az[GR], anx[GR], anh[GR];
    #pragma unroll
    for (int r = 0; r < GR; r++){ ar[r] = az[r] = anx[r] = anh[r] = 0.0f; }

    const float4* Wr = (const float4*)(W_ih + (size_t)j * HH);
    const float4* Wz = (const float4*)(W_ih + (size_t)(HH + j) * HH);
    const float4* Wn = (const float4*)(W_ih + (size_t)(2 * HH + j) * HH);
    const float4* Vr = (const float4*)(W_hh + (size_t)j * HH);
    const float4* Vz = (const float4*)(W_hh + (size_t)(HH + j) * HH);
    const float4* Vn = (const float4*)(W_hh + (size_t)(2 * HH + j) * HH);

    for (int h4 = 0; h4 < HH / 4; h4++){
        float4 wr = Wr[h4], wz = Wz[h4], wn = Wn[h4];
        float4 vr = Vr[h4], vz = Vz[h4], vn = Vn[h4];
        #pragma unroll
        for (int r = 0; r < GR; r++){
            float4 xx = *(const float4*)&x_s[r][h4 * 4];
            float4 hh = *(const float4*)&h_s[r][h4 * 4];
            ar[r]  += wr.x*xx.x + wr.y*xx.y + wr.z*xx.z + wr.w*xx.w
                    + vr.x*hh.x + vr.y*hh.y + vr.z*hh.z + vr.w*hh.w;
            az[r]  += wz.x*xx.x + wz.y*xx.y + wz.z*xx.z + wz.w*xx.w
                    + vz.x*hh.x + vz.y*hh.y + vz.z*hh.z + vz.w*hh.w;
            anx[r] += wn.x*xx.x + wn.y*xx.y + wn.z*xx.z + wn.w*xx.w;
            anh[r] += vn.x*hh.x + vn.y*hh.y + vn.z*hh.z + vn.w*hh.w;
        }
    }
    const float br  = b_ih[j] + b_hh[j];
    const float bz  = b_ih[HH + j] + b_hh[HH + j];
    const float bnx = b_ih[2 * HH + j];
    const float bnh = b_hh[2 * HH + j];
    #pragma unroll
    for (int r = 0; r < GR; r++){
        float rr = 1.0f / (1.0f + expf(-(ar[r] + br)));
        float zz = 1.0f / (1.0f + expf(-(az[r] + bz)));
        float nn = tanhf(anx[r] + bnx + rr * (anh[r] + bnh));
        float hp = (1.0f - zz) * nn + zz * h_s[r][j];
        hn_s[r][j] = hp;
        g_state[(n0 + r) * HH + j] = hp;
    }
    __syncthreads();
    float aq[GR];
    #pragma unroll
    for (int r = 0; r < GR; r++) aq[r] = 0.0f;
    const float4* Q = (const float4*)(Wq + (size_t)j * HH);
    for (int h4 = 0; h4 < HH / 4; h4++){
        float4 wq = Q[h4];
        #pragma unroll
        for (int r = 0; r < GR; r++){
            float4 hh = *(const float4*)&hn_s[r][h4 * 4];
            aq[r] += wq.x*hh.x + wq.y*hh.y + wq.z*hh.z + wq.w*hh.w;
        }
    }
    #pragma unroll
    for (int r = 0; r < GR; r++) g_q[(n0 + r) * HH + j] = aq[r];
}

// ---------------- fused k-GEMM + step-1 score ----------------
// grid (32, 1024): blockIdx.y = n, blockIdx.x = 64-row L-tile.
// 256 threads: lane to = tid&31 owns outputs o = 4*to+oi; warp tr = tid>>5
// owns rows l = l0 + tr + 8*rr (rr 0..7).
// Wk read through the pre-transposed g_WkT: lane-contiguous float4 loads
// (nL=4 per LDG instead of 32), 64 KB stays L1-resident.
// eo loads are warp-uniform (1 wavefront each).
__global__ void __launch_bounds__(256) kq_kernel(
    const float* __restrict__ eo,
    const float* __restrict__ w_score, const float* __restrict__ q)
{
    const int n  = blockIdx.y;
    const int l0 = blockIdx.x * 64;
    const int to = threadIdx.x & 31;
    const int tr = threadIdx.x >> 5;

    unsigned long long acc[4][8];
    #pragma unroll
    for (int oi = 0; oi < 4; oi++)
        #pragma unroll
        for (int rr = 0; rr < 8; rr++) acc[oi][rr] = 0ULL;

    const float* wt_b = g_WkT + 4 * to;                       // column base
    const float* eo_b = eo + ((size_t)n * LL + l0 + tr) * HH;

    #pragma unroll 8
    for (int h4 = 0; h4 < HH / 4; h4++){
        // WkT rows h4*4 .. h4*4+3, 4 consecutive outputs per lane
        float4 wt0 = *(const float4*)(wt_b + (h4 * 4 + 0) * HH);
        float4 wt1 = *(const float4*)(wt_b + (h4 * 4 + 1) * HH);
        float4 wt2 = *(const float4*)(wt_b + (h4 * 4 + 2) * HH);
        float4 wt3 = *(const float4*)(wt_b + (h4 * 4 + 3) * HH);
        // pack (h0,h1) and (h2,h3) pairs per output oi
        unsigned long long w01[4], w23[4];
        w01[0] = pack2(wt0.x, wt1.x);  w23[0] = pack2(wt2.x, wt3.x);
        w01[1] = pack2(wt0.y, wt1.y);  w23[1] = pack2(wt2.y, wt3.y);
        w01[2] = pack2(wt0.z, wt1.z);  w23[2] = pack2(wt2.z, wt3.z);
        w01[3] = pack2(wt0.w, wt1.w);  w23[3] = pack2(wt2.w, wt3.w);
        #pragma unroll
        for (int rr = 0; rr < 8; rr++){
            ulonglong2 e = *(const ulonglong2*)(eo_b + rr * 8 * HH + h4 * 4);
            #pragma unroll
            for (int oi = 0; oi < 4; oi++){
                FMA2(acc[oi][rr], w01[oi], e.x);
                FMA2(acc[oi][rr], w23[oi], e.y);
            }
        }
    }

    const float4 qv = *(const float4*)(q + (size_t)n * HH + 4 * to);
    const float4 wv = *(const float4*)(w_score + 4 * to);

    #pragma unroll
    for (int rr = 0; rr < 8; rr++){
        const int l = l0 + tr + 8 * rr;
        float kv[4];
        #pragma unroll
        for (int oi = 0; oi < 4; oi++){
            unsigned long long a = acc[oi][rr];
            float lo = __uint_as_float((unsigned)(a & 0xffffffffULL));
            float hi = __uint_as_float((unsigned)(a >> 32));
            kv[oi] = lo + hi;
        }
        *(float4*)(g_k + ((size_t)n * LL + l) * HH + 4 * to) =
            make_float4(kv[0], kv[1], kv[2], kv[3]);

        float s = wv.x * acc_tanh(qv.x + kv[0])
                + wv.y * acc_tanh(qv.y + kv[1])
                + wv.z * acc_tanh(qv.z + kv[2])
                + wv.w * acc_tanh(qv.w + kv[3]);
        #pragma unroll
        for (int off = 16; off > 0; off >>= 1)
            s += __shfl_xor_sync(0xffffffffu, s, off);
        if (to == 0) g_logits[(size_t)n * LL + l] = s;
    }
}

// ---------------- step-2 score: read k scratch ----------------
// 8 warps/block, warp = one (n,l) row; memory bound.
__global__ void __launch_bounds__(256) score2_kernel(
    const float* __restrict__ w_score, const float* __restrict__ q)
{
    const size_t row  = (size_t)blockIdx.x * 8 + (threadIdx.x >> 5);
    const int    lane = threadIdx.x & 31;
    const int    n    = (int)(row >> 11);           // row / LL

    const float4 kv = *(const float4*)(g_k + row * HH + 4 * lane);
    const float4 qv = *(const float4*)(q + (size_t)n * HH + 4 * lane);
    const float4 wv = *(const float4*)(w_score + 4 * lane);

    float s = wv.x * acc_tanh(qv.x + kv.x)
            + wv.y * acc_tanh(qv.y + kv.y)
            + wv.z * acc_tanh(qv.z + kv.z)
            + wv.w * acc_tanh(qv.w + kv.w);
    #pragma unroll
    for (int off = 16; off > 0; off >>= 1)
        s += __shfl_xor_sync(0xffffffffu, s, off);
    if (lane == 0) g_logits[row] = s;
}

// ---------------- softmax + argmax (+ gather next input) ----------------
// block per n, 256 threads, 8 logits/thread.
__global__ void __launch_bounds__(256) softmax_kernel(
    const float* __restrict__ enc_in, float* __restrict__ out,
    int step, int do_gather)
{
    __shared__ float smax[256];
    __shared__ int   sidx[256];
    __shared__ float ssum[256];
    const int n   = blockIdx.x;
    const int tid = threadIdx.x;
    const float* lg = g_logits + (size_t)n * LL;

    float v[8];
    float vmax = -1e30f; int vidx = 0;
    #pragma unroll
    for (int i = 0; i < 8; i++){
        int l = tid + i * 256;
        v[i] = lg[l];
        if (v[i] > vmax){ vmax = v[i]; vidx = l; }
    }
    smax[tid] = vmax; sidx[tid] = vidx;
    __syncthreads();
    for (int s = 128; s > 0; s >>= 1){
        if (tid < s){
            float ov = smax[tid + s]; int oi = sidx[tid + s];
            if (ov > smax[tid] || (ov == smax[tid] && oi < sidx[tid])){
                smax[tid] = ov; sidx[tid] = oi;
            }
        }
        __syncthreads();
    }
    const float m   = smax[0];
    const int   idx = sidx[0];
    __syncthreads();

    float e[8];
    float loc = 0.0f;
    #pragma unroll
    for (int i = 0; i < 8; i++){ e[i] = expf(v[i] - m); loc += e[i]; }
    ssum[tid] = loc;
    __syncthreads();
    for (int s = 128; s > 0; s >>= 1){
        if (tid < s) ssum[tid] += ssum[tid + s];
        __syncthreads();
    }
    const float inv = 1.0f / ssum[0];

    float* orow = out + ((size_t)n * 2 + step) * LL;
    #pragma unroll
    for (int i = 0; i < 8; i++) orow[tid + i * 256] = e[i] * inv;

    if (do_gather && tid < HH)
        g_x[n * HH + tid] = enc_in[((size_t)n * LL + idx) * HH + tid];
}

// ---------------- launch ----------------
extern "C" void kernel_launch(void* const* d_in, const int* in_sizes, int n_in,
                              void* d_out, int out_size)
{
    const float* enc_in  = (const float*)d_in[0];
    const float* enc_out = (const float*)d_in[1];
    const float* state0  = (const float*)d_in[2];
    const float* W_ih    = (const float*)d_in[3];
    const float* W_hh    = (const float*)d_in[4];
    const float* b_ih    = (const float*)d_in[5];
    const float* b_hh    = (const float*)d_in[6];
    const float* Wq      = (const float*)d_in[7];
    const float* Wk      = (const float*)d_in[8];
    const float* w_score = (const float*)d_in[9];
    float* out = (float*)d_out;

    float *p_x, *p_state, *p_q;
    cudaGetSymbolAddress((void**)&p_x, g_x);
    cudaGetSymbolAddress((void**)&p_state, g_state);
    cudaGetSymbolAddress((void**)&p_q, g_q);

    // prologue
    init_x_kernel<<<(NN * HH + 255) / 256, 256>>>();
    transpose_wk_kernel<<<HH, HH>>>(Wk);
    // step 1
    gru_kernel<<<NN / GR, HH>>>(p_x, state0, W_ih, W_hh, b_ih, b_hh, Wq);
    kq_kernel<<<dim3(LL / 64, NN), 256>>>(enc_out, w_score, p_q);
    softmax_kernel<<<NN, 256>>>(enc_in, out, 0, 1);
    // step 2
    gru_kernel<<<NN / GR, HH>>>(p_x, p_state, W_ih, W_hh, b_ih, b_hh, Wq);
    score2_kernel<<<(int)(((size_t)NN * LL) / 8), 256>>>(w_score, p_q);
    softmax_kernel<<<NN, 256>>>(enc_in, out, 1, 0);
}

// round 9
// speedup vs baseline: 1.7809x; 1.3261x over previous
#include <cuda_runtime.h>
#include <cuda_bf16.h>
#include <cstdint>
#include <cstddef>
#include <math.h>

#define NN 1024
#define LL 2048
#define HH 128

// ---------------- scratch (device globals; no allocation) ----------------
static __device__ float g_k[(size_t)NN * LL * HH];   // 1 GiB
static __device__ float g_logits[(size_t)NN * LL];
static __device__ float g_x[NN * HH];
static __device__ float g_state[NN * HH];
static __device__ float g_q[NN * HH];
// Wk pre-paired: g_Wp[h2*128 + o] = (Wk[o][2*h2], Wk[o][2*h2+1]) as u64
static __device__ unsigned long long g_Wp[(HH / 2) * HH];

// ---------------- math helpers ----------------
__device__ __forceinline__ float ex2f(float x){ float r; asm("ex2.approx.f32 %0, %1;" : "=f"(r) : "f"(x)); return r; }
__device__ __forceinline__ float rcpaf(float x){ float r; asm("rcp.approx.f32 %0, %1;" : "=f"(r) : "f"(x)); return r; }

// tanh(x) = 1 - 2/(1+e^{2x}); ex2 + rcp + one Newton step  (~1e-7 abs err)
__device__ __forceinline__ float acc_tanh(float x){
    float y = fminf(x * 2.8853900817779268f, 80.0f);   // 2/ln(2)
    float e = ex2f(y);
    float d = e + 1.0f;
    float r = rcpaf(d);
    r = r * fmaf(-d, r, 2.0f);                         // Newton
    return fmaf(-2.0f, r, 1.0f);
}

#define FMA2(d, a, b) asm("fma.rn.f32x2 %0, %1, %2, %0;" : "+l"(d) : "l"(a), "l"(b))

__device__ __forceinline__ unsigned long long pack2(float lo, float hi){
    return (unsigned long long)__float_as_uint(lo)
         | ((unsigned long long)__float_as_uint(hi) << 32);
}

// ---------------- init decoder input to ones ----------------
__global__ void init_x_kernel(){
    int i = blockIdx.x * blockDim.x + threadIdx.x;
    if (i < NN * HH) g_x[i] = 1.0f;
}

// ---------------- build paired-weight layout (64 KB, once per replay) ----
__global__ void __launch_bounds__(HH) pair_wk_kernel(const float* __restrict__ Wk){
    const int h2 = blockIdx.x;      // 64 blocks
    const int o  = threadIdx.x;     // 128 threads
    g_Wp[h2 * HH + o] = pack2(Wk[o * HH + 2 * h2], Wk[o * HH + 2 * h2 + 1]);
}

// ---------------- GRU cell + q projection ----------------
#define GR 8
__global__ void __launch_bounds__(HH) gru_kernel(
    const float* __restrict__ x_in, const float* __restrict__ h_in,
    const float* __restrict__ W_ih, const float* __restrict__ W_hh,
    const float* __restrict__ b_ih, const float* __restrict__ b_hh,
    const float* __restrict__ Wq)
{
    __shared__ float x_s[GR][HH];
    __shared__ float h_s[GR][HH];
    __shared__ float hn_s[GR][HH];
    const int n0 = blockIdx.x * GR;
    const int j  = threadIdx.x;
    for (int r = 0; r < GR; r++){
        x_s[r][j] = x_in[(n0 + r) * HH + j];
        h_s[r][j] = h_in[(n0 + r) * HH + j];
    }
    __syncthreads();

    float ar[GR], az[GR], anx[GR], anh[GR];
    #pragma unroll
    for (int r = 0; r < GR; r++){ ar[r] = az[r] = anx[r] = anh[r] = 0.0f; }

    const float4* Wr = (const float4*)(W_ih + (size_t)j * HH);
    const float4* Wz = (const float4*)(W_ih + (size_t)(HH + j) * HH);
    const float4* Wn = (const float4*)(W_ih + (size_t)(2 * HH + j) * HH);
    const float4* Vr = (const float4*)(W_hh + (size_t)j * HH);
    const float4* Vz = (const float4*)(W_hh + (size_t)(HH + j) * HH);
    const float4* Vn = (const float4*)(W_hh + (size_t)(2 * HH + j) * HH);

    for (int h4 = 0; h4 < HH / 4; h4++){
        float4 wr = Wr[h4], wz = Wz[h4], wn = Wn[h4];
        float4 vr = Vr[h4], vz = Vz[h4], vn = Vn[h4];
        #pragma unroll
        for (int r = 0; r < GR; r++){
            float4 xx = *(const float4*)&x_s[r][h4 * 4];
            float4 hh = *(const float4*)&h_s[r][h4 * 4];
            ar[r]  += wr.x*xx.x + wr.y*xx.y + wr.z*xx.z + wr.w*xx.w
                    + vr.x*hh.x + vr.y*hh.y + vr.z*hh.z + vr.w*hh.w;
            az[r]  += wz.x*xx.x + wz.y*xx.y + wz.z*xx.z + wz.w*xx.w
                    + vz.x*hh.x + vz.y*hh.y + vz.z*hh.z + vz.w*hh.w;
            anx[r] += wn.x*xx.x + wn.y*xx.y + wn.z*xx.z + wn.w*xx.w;
            anh[r] += vn.x*hh.x + vn.y*hh.y + vn.z*hh.z + vn.w*hh.w;
        }
    }
    const float br  = b_ih[j] + b_hh[j];
    const float bz  = b_ih[HH + j] + b_hh[HH + j];
    const float bnx = b_ih[2 * HH + j];
    const float bnh = b_hh[2 * HH + j];
    #pragma unroll
    for (int r = 0; r < GR; r++){
        float rr = 1.0f / (1.0f + expf(-(ar[r] + br)));
        float zz = 1.0f / (1.0f + expf(-(az[r] + bz)));
        float nn = tanhf(anx[r] + bnx + rr * (anh[r] + bnh));
        float hp = (1.0f - zz) * nn + zz * h_s[r][j];
        hn_s[r][j] = hp;
        g_state[(n0 + r) * HH + j] = hp;
    }
    __syncthreads();
    float aq[GR];
    #pragma unroll
    for (int r = 0; r < GR; r++) aq[r] = 0.0f;
    const float4* Q = (const float4*)(Wq + (size_t)j * HH);
    for (int h4 = 0; h4 < HH / 4; h4++){
        float4 wq = Q[h4];
        #pragma unroll
        for (int r = 0; r < GR; r++){
            float4 hh = *(const float4*)&hn_s[r][h4 * 4];
            aq[r] += wq.x*hh.x + wq.y*hh.y + wq.z*hh.z + wq.w*hh.w;
        }
    }
    #pragma unroll
    for (int r = 0; r < GR; r++) g_q[(n0 + r) * HH + j] = aq[r];
}

// ---------------- fused k-GEMM + step-1 score ----------------
// grid (32, 1024): blockIdx.y = n, blockIdx.x = 64-row L-tile.
// 256 threads, 8 warps. Warp w: oh = w&1 selects o-half (64 outputs),
// rg = w>>1 selects 16-row group. Lane owns 2 outputs o0 = oh*64 + 2*lane
// and 16 rows rr. Accumulators are packed f32x2 over (even-h, odd-h)
// partial sums; weights come pre-paired from g_Wp (no MOV packing).
__global__ void __launch_bounds__(256, 2) kq_kernel(
    const float* __restrict__ eo,
    const float* __restrict__ w_score, const float* __restrict__ q)
{
    __shared__ float part[2][64];
    const int n    = blockIdx.y;
    const int l0   = blockIdx.x * 64;
    const int w    = threadIdx.x >> 5;
    const int lane = threadIdx.x & 31;
    const int oh   = w & 1;
    const int rg   = w >> 1;
    const int o0   = oh * 64 + 2 * lane;
    const int lr0  = l0 + rg * 16;

    unsigned long long acc0[16], acc1[16];
    #pragma unroll
    for (int rr = 0; rr < 16; rr++){ acc0[rr] = 0ULL; acc1[rr] = 0ULL; }

    const unsigned long long* wp = g_Wp + o0;                  // + h2*128
    const float* eo_b = eo + ((size_t)n * LL + lr0) * HH;

    #pragma unroll 4
    for (int h2 = 0; h2 < HH / 2; h2 += 2){
        // weight pairs for outputs (o0, o0+1) at h2 and h2+1
        ulonglong2 wA = *(const ulonglong2*)(wp + (size_t)h2 * HH);
        ulonglong2 wB = *(const ulonglong2*)(wp + (size_t)(h2 + 1) * HH);
        #pragma unroll
        for (int rr = 0; rr < 16; rr++){
            // e.x = (eo[2h2], eo[2h2+1]), e.y = (eo[2h2+2], eo[2h2+3])
            ulonglong2 e = *(const ulonglong2*)(eo_b + (size_t)rr * HH + 2 * h2);
            FMA2(acc0[rr], wA.x, e.x);
            FMA2(acc1[rr], wA.y, e.x);
            FMA2(acc0[rr], wB.x, e.y);
            FMA2(acc1[rr], wB.y, e.y);
        }
    }

    const float qv0 = q[(size_t)n * HH + o0];
    const float qv1 = q[(size_t)n * HH + o0 + 1];
    const float wv0 = w_score[o0];
    const float wv1 = w_score[o0 + 1];

    #pragma unroll
    for (int rr = 0; rr < 16; rr++){
        const int l = lr0 + rr;
        float k0 = __uint_as_float((unsigned)(acc0[rr] & 0xffffffffULL))
                 + __uint_as_float((unsigned)(acc0[rr] >> 32));
        float k1 = __uint_as_float((unsigned)(acc1[rr] & 0xffffffffULL))
                 + __uint_as_float((unsigned)(acc1[rr] >> 32));
        *(float2*)(g_k + ((size_t)n * LL + l) * HH + o0) = make_float2(k0, k1);

        float s = wv0 * acc_tanh(qv0 + k0) + wv1 * acc_tanh(qv1 + k1);
        #pragma unroll
        for (int off = 16; off > 0; off >>= 1)
            s += __shfl_xor_sync(0xffffffffu, s, off);
        if (lane == 0) part[oh][rg * 16 + rr] = s;
    }
    __syncthreads();
    if (threadIdx.x < 64)
        g_logits[(size_t)n * LL + l0 + threadIdx.x] =
            part[0][threadIdx.x] + part[1][threadIdx.x];
}

// ---------------- step-2 score: read k scratch ----------------
__global__ void __launch_bounds__(256) score2_kernel(
    const float* __restrict__ w_score, const float* __restrict__ q)
{
    const size_t row  = (size_t)blockIdx.x * 8 + (threadIdx.x >> 5);
    const int    lane = threadIdx.x & 31;
    const int    n    = (int)(row >> 11);           // row / LL

    const float4 kv = *(const float4*)(g_k + row * HH + 4 * lane);
    const float4 qv = *(const float4*)(q + (size_t)n * HH + 4 * lane);
    const float4 wv = *(const float4*)(w_score + 4 * lane);

    float s = wv.x * acc_tanh(qv.x + kv.x)
            + wv.y * acc_tanh(qv.y + kv.y)
            + wv.z * acc_tanh(qv.z + kv.z)
            + wv.w * acc_tanh(qv.w + kv.w);
    #pragma unroll
    for (int off = 16; off > 0; off >>= 1)
        s += __shfl_xor_sync(0xffffffffu, s, off);
    if (lane == 0) g_logits[row] = s;
}

// ---------------- softmax + argmax (+ gather next input) ----------------
__global__ void __launch_bounds__(256) softmax_kernel(
    const float* __restrict__ enc_in, float* __restrict__ out,
    int step, int do_gather)
{
    __shared__ float smax[256];
    __shared__ int   sidx[256];
    __shared__ float ssum[256];
    const int n   = blockIdx.x;
    const int tid = threadIdx.x;
    const float* lg = g_logits + (size_t)n * LL;

    float v[8];
    float vmax = -1e30f; int vidx = 0;
    #pragma unroll
    for (int i = 0; i < 8; i++){
        int l = tid + i * 256;
        v[i] = lg[l];
        if (v[i] > vmax){ vmax = v[i]; vidx = l; }
    }
    smax[tid] = vmax; sidx[tid] = vidx;
    __syncthreads();
    for (int s = 128; s > 0; s >>= 1){
        if (tid < s){
            float ov = smax[tid + s]; int oi = sidx[tid + s];
            if (ov > smax[tid] || (ov == smax[tid] && oi < sidx[tid])){
                smax[tid] = ov; sidx[tid] = oi;
            }
        }
        __syncthreads();
    }
    const float m   = smax[0];
    const int   idx = sidx[0];
    __syncthreads();

    float e[8];
    float loc = 0.0f;
    #pragma unroll
    for (int i = 0; i < 8; i++){ e[i] = expf(v[i] - m); loc += e[i]; }
    ssum[tid] = loc;
    __syncthreads();
    for (int s = 128; s > 0; s >>= 1){
        if (tid < s) ssum[tid] += ssum[tid + s];
        __syncthreads();
    }
    const float inv = 1.0f / ssum[0];

    float* orow = out + ((size_t)n * 2 + step) * LL;
    #pragma unroll
    for (int i = 0; i < 8; i++) orow[tid + i * 256] = e[i] * inv;

    if (do_gather && tid < HH)
        g_x[n * HH + tid] = enc_in[((size_t)n * LL + idx) * HH + tid];
}

// ---------------- launch ----------------
extern "C" void kernel_launch(void* const* d_in, const int* in_sizes, int n_in,
                              void* d_out, int out_size)
{
    const float* enc_in  = (const float*)d_in[0];
    const float* enc_out = (const float*)d_in[1];
    const float* state0  = (const float*)d_in[2];
    const float* W_ih    = (const float*)d_in[3];
    const float* W_hh    = (const float*)d_in[4];
    const float* b_ih    = (const float*)d_in[5];
    const float* b_hh    = (const float*)d_in[6];
    const float* Wq      = (const float*)d_in[7];
    const float* Wk      = (const float*)d_in[8];
    const float* w_score = (const float*)d_in[9];
    float* out = (float*)d_out;

    float *p_x, *p_state, *p_q;
    cudaGetSymbolAddress((void**)&p_x, g_x);
    cudaGetSymbolAddress((void**)&p_state, g_state);
    cudaGetSymbolAddress((void**)&p_q, g_q);

    // prologue
    init_x_kernel<<<(NN * HH + 255) / 256, 256>>>();
    pair_wk_kernel<<<HH / 2, HH>>>(Wk);
    // step 1
    gru_kernel<<<NN / GR, HH>>>(p_x, state0, W_ih, W_hh, b_ih, b_hh, Wq);
    kq_kernel<<<dim3(LL / 64, NN), 256>>>(enc_out, w_score, p_q);
    softmax_kernel<<<NN, 256>>>(enc_in, out, 0, 1);
    // step 2
    gru_kernel<<<NN / GR, HH>>>(p_x, p_state, W_ih, W_hh, b_ih, b_hh, Wq);
    score2_kernel<<<(int)(((size_t)NN * LL) / 8), 256>>>(w_score, p_q);
    softmax_kernel<<<NN, 256>>>(enc_in, out, 1, 0);
}

// round 12
// speedup vs baseline: 2.3065x; 1.2951x over previous
#include <cuda_runtime.h>
#include <cuda_bf16.h>
#include <cstdint>
#include <cstddef>
#include <math.h>

#define NN 1024
#define LL 2048
#define HH 128

// ---------------- scratch (device globals; no allocation) ----------------
static __device__ float g_k[(size_t)NN * LL * HH];   // 1 GiB
static __device__ float g_logits[(size_t)NN * LL];
static __device__ float g_x[NN * HH];
static __device__ float g_state[NN * HH];
static __device__ float g_q[NN * HH];
// Wk pre-paired: g_Wp[h2*128 + o] = (Wk[o][2*h2], Wk[o][2*h2+1]) as u64
static __device__ unsigned long long g_Wp[(HH / 2) * HH];

// ---------------- math helpers ----------------
__device__ __forceinline__ float ex2f(float x){ float r; asm("ex2.approx.f32 %0, %1;" : "=f"(r) : "f"(x)); return r; }
__device__ __forceinline__ float rcpaf(float x){ float r; asm("rcp.approx.f32 %0, %1;" : "=f"(r) : "f"(x)); return r; }

// tanh(x) = 1 - 2/(1+e^{2x}); ex2 + rcp + one Newton step  (~1e-7 abs err)
__device__ __forceinline__ float acc_tanh(float x){
    float y = fminf(x * 2.8853900817779268f, 80.0f);   // 2/ln(2)
    float e = ex2f(y);
    float d = e + 1.0f;
    float r = rcpaf(d);
    r = r * fmaf(-d, r, 2.0f);                         // Newton
    return fmaf(-2.0f, r, 1.0f);
}

#define FMA2(d, a, b) asm("fma.rn.f32x2 %0, %1, %2, %0;" : "+l"(d) : "l"(a), "l"(b))

__device__ __forceinline__ unsigned long long pack2(float lo, float hi){
    return (unsigned long long)__float_as_uint(lo)
         | ((unsigned long long)__float_as_uint(hi) << 32);
}

// ---------------- init decoder input to ones ----------------
__global__ void init_x_kernel(){
    int i = blockIdx.x * blockDim.x + threadIdx.x;
    if (i < NN * HH) g_x[i] = 1.0f;
}

// ---------------- build paired-weight layout (64 KB, once per replay) ----
__global__ void __launch_bounds__(HH) pair_wk_kernel(const float* __restrict__ Wk){
    const int h2 = blockIdx.x;      // 64 blocks
    const int o  = threadIdx.x;     // 128 threads
    g_Wp[h2 * HH + o] = pack2(Wk[o * HH + 2 * h2], Wk[o * HH + 2 * h2 + 1]);
}

// ---------------- GRU cell + q projection ----------------
#define GR 8
__global__ void __launch_bounds__(HH) gru_kernel(
    const float* __restrict__ x_in, const float* __restrict__ h_in,
    const float* __restrict__ W_ih, const float* __restrict__ W_hh,
    const float* __restrict__ b_ih, const float* __restrict__ b_hh,
    const float* __restrict__ Wq)
{
    __shared__ float x_s[GR][HH];
    __shared__ float h_s[GR][HH];
    __shared__ float hn_s[GR][HH];
    const int n0 = blockIdx.x * GR;
    const int j  = threadIdx.x;
    for (int r = 0; r < GR; r++){
        x_s[r][j] = x_in[(n0 + r) * HH + j];
        h_s[r][j] = h_in[(n0 + r) * HH + j];
    }
    __syncthreads();

    float ar[GR], az[GR], anx[GR], anh[GR];
    #pragma unroll
    for (int r = 0; r < GR; r++){ ar[r] = az[r] = anx[r] = anh[r] = 0.0f; }

    const float4* Wr = (const float4*)(W_ih + (size_t)j * HH);
    const float4* Wz = (const float4*)(W_ih + (size_t)(HH + j) * HH);
    const float4* Wn = (const float4*)(W_ih + (size_t)(2 * HH + j) * HH);
    const float4* Vr = (const float4*)(W_hh + (size_t)j * HH);
    const float4* Vz = (const float4*)(W_hh + (size_t)(HH + j) * HH);
    const float4* Vn = (const float4*)(W_hh + (size_t)(2 * HH + j) * HH);

    for (int h4 = 0; h4 < HH / 4; h4++){
        float4 wr = Wr[h4], wz = Wz[h4], wn = Wn[h4];
        float4 vr = Vr[h4], vz = Vz[h4], vn = Vn[h4];
        #pragma unroll
        for (int r = 0; r < GR; r++){
            float4 xx = *(const float4*)&x_s[r][h4 * 4];
            float4 hh = *(const float4*)&h_s[r][h4 * 4];
            ar[r]  += wr.x*xx.x + wr.y*xx.y + wr.z*xx.z + wr.w*xx.w
                    + vr.x*hh.x + vr.y*hh.y + vr.z*hh.z + vr.w*hh.w;
            az[r]  += wz.x*xx.x + wz.y*xx.y + wz.z*xx.z + wz.w*xx.w
                    + vz.x*hh.x + vz.y*hh.y + vz.z*hh.z + vz.w*hh.w;
            anx[r] += wn.x*xx.x + wn.y*xx.y + wn.z*xx.z + wn.w*xx.w;
            anh[r] += vn.x*hh.x + vn.y*hh.y + vn.z*hh.z + vn.w*hh.w;
        }
    }
    const float br  = b_ih[j] + b_hh[j];
    const float bz  = b_ih[HH + j] + b_hh[HH + j];
    const float bnx = b_ih[2 * HH + j];
    const float bnh = b_hh[2 * HH + j];
    #pragma unroll
    for (int r = 0; r < GR; r++){
        float rr = 1.0f / (1.0f + expf(-(ar[r] + br)));
        float zz = 1.0f / (1.0f + expf(-(az[r] + bz)));
        float nn = tanhf(anx[r] + bnx + rr * (anh[r] + bnh));
        float hp = (1.0f - zz) * nn + zz * h_s[r][j];
        hn_s[r][j] = hp;
        g_state[(n0 + r) * HH + j] = hp;
    }
    __syncthreads();
    float aq[GR];
    #pragma unroll
    for (int r = 0; r < GR; r++) aq[r] = 0.0f;
    const float4* Q = (const float4*)(Wq + (size_t)j * HH);
    for (int h4 = 0; h4 < HH / 4; h4++){
        float4 wq = Q[h4];
        #pragma unroll
        for (int r = 0; r < GR; r++){
            float4 hh = *(const float4*)&hn_s[r][h4 * 4];
            aq[r] += wq.x*hh.x + wq.y*hh.y + wq.z*hh.z + wq.w*hh.w;
        }
    }
    #pragma unroll
    for (int r = 0; r < GR; r++) g_q[(n0 + r) * HH + j] = aq[r];
}

// ---------------- fused k-GEMM + step-1 score ----------------
// grid (32, 1024): blockIdx.y = n, blockIdx.x = 64-row L-tile.
// 256 threads, 8 warps. eo tile (64x128 fp32, 32 KB) is staged to smem
// once per block; mainloop reads it via broadcast LDS (no L1 writeback
// storm). Warp w: oh = w&1 selects o-half, rg = w>>1 selects 16-row group.
// Lane owns 2 outputs o0 = oh*64 + 2*lane; accumulators are packed f32x2
// over (even-h, odd-h) partial sums; weights pre-paired in g_Wp (L1-hot).
__global__ void __launch_bounds__(256, 2) kq_kernel(
    const float* __restrict__ eo,
    const float* __restrict__ w_score, const float* __restrict__ q)
{
    __shared__ float eo_s[64 * HH];       // 32 KB
    __shared__ float part[2][64];
    const int n    = blockIdx.y;
    const int l0   = blockIdx.x * 64;
    const int w    = threadIdx.x >> 5;
    const int lane = threadIdx.x & 31;
    const int oh   = w & 1;
    const int rg   = w >> 1;
    const int o0   = oh * 64 + 2 * lane;

    // stage eo tile: 2048 float4, 8 per thread, coalesced
    {
        const float4* src = (const float4*)(eo + ((size_t)n * LL + l0) * HH);
        float4* dst = (float4*)eo_s;
        #pragma unroll
        for (int it = 0; it < 8; it++)
            dst[threadIdx.x + it * 256] = src[threadIdx.x + it * 256];
    }
    __syncthreads();

    unsigned long long acc0[16], acc1[16];
    #pragma unroll
    for (int rr = 0; rr < 16; rr++){ acc0[rr] = 0ULL; acc1[rr] = 0ULL; }

    const unsigned long long* wp = g_Wp + o0;                  // + h2*128
    const float* eo_b = eo_s + rg * 16 * HH;

    #pragma unroll 4
    for (int h2 = 0; h2 < HH / 2; h2 += 2){
        // weight pairs for outputs (o0, o0+1) at h2 and h2+1
        ulonglong2 wA = *(const ulonglong2*)(wp + (size_t)h2 * HH);
        ulonglong2 wB = *(const ulonglong2*)(wp + (size_t)(h2 + 1) * HH);
        #pragma unroll
        for (int rr = 0; rr < 16; rr++){
            // e.x = (eo[2h2], eo[2h2+1]), e.y = (eo[2h2+2], eo[2h2+3])
            ulonglong2 e = *(const ulonglong2*)(eo_b + rr * HH + 2 * h2);
            FMA2(acc0[rr], wA.x, e.x);
            FMA2(acc1[rr], wA.y, e.x);
            FMA2(acc0[rr], wB.x, e.y);
            FMA2(acc1[rr], wB.y, e.y);
        }
    }

    const float qv0 = q[(size_t)n * HH + o0];
    const float qv1 = q[(size_t)n * HH + o0 + 1];
    const float wv0 = w_score[o0];
    const float wv1 = w_score[o0 + 1];
    const int lr0 = l0 + rg * 16;

    #pragma unroll
    for (int rr = 0; rr < 16; rr++){
        const int l = lr0 + rr;
        float k0 = __uint_as_float((unsigned)(acc0[rr] & 0xffffffffULL))
                 + __uint_as_float((unsigned)(acc0[rr] >> 32));
        float k1 = __uint_as_float((unsigned)(acc1[rr] & 0xffffffffULL))
                 + __uint_as_float((unsigned)(acc1[rr] >> 32));
        *(float2*)(g_k + ((size_t)n * LL + l) * HH + o0) = make_float2(k0, k1);

        float s = wv0 * acc_tanh(qv0 + k0) + wv1 * acc_tanh(qv1 + k1);
        #pragma unroll
        for (int off = 16; off > 0; off >>= 1)
            s += __shfl_xor_sync(0xffffffffu, s, off);
        if (lane == 0) part[oh][rg * 16 + rr] = s;
    }
    __syncthreads();
    if (threadIdx.x < 64)
        g_logits[(size_t)n * LL + l0 + threadIdx.x] =
            part[0][threadIdx.x] + part[1][threadIdx.x];
}

// ---------------- step-2 score: read k scratch ----------------
__global__ void __launch_bounds__(256) score2_kernel(
    const float* __restrict__ w_score, const float* __restrict__ q)
{
    const size_t row  = (size_t)blockIdx.x * 8 + (threadIdx.x >> 5);
    const int    lane = threadIdx.x & 31;
    const int    n    = (int)(row >> 11);           // row / LL

    const float4 kv = *(const float4*)(g_k + row * HH + 4 * lane);
    const float4 qv = *(const float4*)(q + (size_t)n * HH + 4 * lane);
    const float4 wv = *(const float4*)(w_score + 4 * lane);

    float s = wv.x * acc_tanh(qv.x + kv.x)
            + wv.y * acc_tanh(qv.y + kv.y)
            + wv.z * acc_tanh(qv.z + kv.z)
            + wv.w * acc_tanh(qv.w + kv.w);
    #pragma unroll
    for (int off = 16; off > 0; off >>= 1)
        s += __shfl_xor_sync(0xffffffffu, s, off);
    if (lane == 0) g_logits[row] = s;
}

// ---------------- softmax + argmax (+ gather next input) ----------------
__global__ void __launch_bounds__(256) softmax_kernel(
    const float* __restrict__ enc_in, float* __restrict__ out,
    int step, int do_gather)
{
    __shared__ float smax[256];
    __shared__ int   sidx[256];
    __shared__ float ssum[256];
    const int n   = blockIdx.x;
    const int tid = threadIdx.x;
    const float* lg = g_logits + (size_t)n * LL;

    float v[8];
    float vmax = -1e30f; int vidx = 0;
    #pragma unroll
    for (int i = 0; i < 8; i++){
        int l = tid + i * 256;
        v[i] = lg[l];
        if (v[i] > vmax){ vmax = v[i]; vidx = l; }
    }
    smax[tid] = vmax; sidx[tid] = vidx;
    __syncthreads();
    for (int s = 128; s > 0; s >>= 1){
        if (tid < s){
            float ov = smax[tid + s]; int oi = sidx[tid + s];
            if (ov > smax[tid] || (ov == smax[tid] && oi < sidx[tid])){
                smax[tid] = ov; sidx[tid] = oi;
            }
        }
        __syncthreads();
    }
    const float m   = smax[0];
    const int   idx = sidx[0];
    __syncthreads();

    float e[8];
    float loc = 0.0f;
    #pragma unroll
    for (int i = 0; i < 8; i++){ e[i] = expf(v[i] - m); loc += e[i]; }
    ssum[tid] = loc;
    __syncthreads();
    for (int s = 128; s > 0; s >>= 1){
        if (tid < s) ssum[tid] += ssum[tid + s];
        __syncthreads();
    }
    const float inv = 1.0f / ssum[0];

    float* orow = out + ((size_t)n * 2 + step) * LL;
    #pragma unroll
    for (int i = 0; i < 8; i++) orow[tid + i * 256] = e[i] * inv;

    if (do_gather && tid < HH)
        g_x[n * HH + tid] = enc_in[((size_t)n * LL + idx) * HH + tid];
}

// ---------------- launch ----------------
extern "C" void kernel_launch(void* const* d_in, const int* in_sizes, int n_in,
                              void* d_out, int out_size)
{
    const float* enc_in  = (const float*)d_in[0];
    const float* enc_out = (const float*)d_in[1];
    const float* state0  = (const float*)d_in[2];
    const float* W_ih    = (const float*)d_in[3];
    const float* W_hh    = (const float*)d_in[4];
    const float* b_ih    = (const float*)d_in[5];
    const float* b_hh    = (const float*)d_in[6];
    const float* Wq      = (const float*)d_in[7];
    const float* Wk      = (const float*)d_in[8];
    const float* w_score = (const float*)d_in[9];
    float* out = (float*)d_out;

    float *p_x, *p_state, *p_q;
    cudaGetSymbolAddress((void**)&p_x, g_x);
    cudaGetSymbolAddress((void**)&p_state, g_state);
    cudaGetSymbolAddress((void**)&p_q, g_q);

    // prologue
    init_x_kernel<<<(NN * HH + 255) / 256, 256>>>();
    pair_wk_kernel<<<HH / 2, HH>>>(Wk);
    // step 1
    gru_kernel<<<NN / GR, HH>>>(p_x, state0, W_ih, W_hh, b_ih, b_hh, Wq);
    kq_kernel<<<dim3(LL / 64, NN), 256>>>(enc_out, w_score, p_q);
    softmax_kernel<<<NN, 256>>>(enc_in, out, 0, 1);
    // step 2
    gru_kernel<<<NN / GR, HH>>>(p_x, p_state, W_ih, W_hh, b_ih, b_hh, Wq);
    score2_kernel<<<(int)(((size_t)NN * LL) / 8), 256>>>(w_score, p_q);
    softmax_kernel<<<NN, 256>>>(enc_in, out, 1, 0);
}